// round 2
// baseline (speedup 1.0000x reference)
#include <cuda_runtime.h>
#include <math.h>

#define Hh 2048
#define Tt 4096
#define Dd 66
#define G4H (4*Hh)
#define NBLK 148
#define NTHR 512
#define NWARP (NTHR/32)

// Persistent device state (static allocation — allowed; no runtime allocs).
__device__ float g_h1[2][Hh];
__device__ float g_h2[2][Hh];
__device__ float g_h2hist[Tt][Hh];                 // 33.5 MB
__device__ float g_pre1[(size_t)Tt * G4H];         // 134 MB: b_ih1+b_hh1 + W_ih1@y[t]
__device__ unsigned g_bar_count = 0;
__device__ unsigned g_bar_gen = 0;

__device__ __forceinline__ float sigf(float x) { return 1.0f / (1.0f + expf(-x)); }

// Software grid barrier. Requires all NBLK blocks co-resident (1 block/SM,
// NBLK=148 <= 152 SMs on GB300, modest regs/smem -> guaranteed).
__device__ __forceinline__ void grid_barrier() {
    __syncthreads();
    if (threadIdx.x == 0) {
        __threadfence();
        volatile unsigned* genp = &g_bar_gen;
        unsigned gen = *genp;                       // read BEFORE arriving
        if (atomicAdd(&g_bar_count, 1u) == NBLK - 1u) {
            g_bar_count = 0;
            __threadfence();
            atomicAdd(&g_bar_gen, 1u);              // release
        } else {
            while (*genp == gen) { __nanosleep(64); }
        }
    }
    __syncthreads();
}

// Warp-cooperative dot of a 2048-float weight row (global) with a 2048-float
// vector in shared memory. Lane-coalesced float4 loads: 16 iters x 512B/warp.
__device__ __forceinline__ float warp_dot(const float4* __restrict__ w,
                                          const float4* __restrict__ sh,
                                          int lane) {
    float ax = 0.f, ay = 0.f, az = 0.f, aw = 0.f;
#pragma unroll
    for (int k = 0; k < 16; k++) {
        float4 wv = w[k * 32 + lane];
        float4 hv = sh[k * 32 + lane];
        ax += wv.x * hv.x; ay += wv.y * hv.y;
        az += wv.z * hv.z; aw += wv.w * hv.w;
    }
    float s = (ax + ay) + (az + aw);
#pragma unroll
    for (int off = 16; off; off >>= 1) s += __shfl_down_sync(0xffffffffu, s, off);
    return s;
}

// ---------------------------------------------------------------------------
// Kernel 1: precompute g_pre1[t][row] = b_ih1[row] + b_hh1[row] + W_ih1[row,:] @ y[t,:]
// grid: (G4H/128, Tt/64), block: 128. Each thread owns one gate row, loops 64 t.
// ---------------------------------------------------------------------------
__global__ void pre1_kernel(const float* __restrict__ y,
                            const float* __restrict__ W_ih1,
                            const float* __restrict__ b_ih1,
                            const float* __restrict__ b_hh1) {
    __shared__ float sy[64 * Dd];
    int row = blockIdx.x * 128 + threadIdx.x;
    int t0 = blockIdx.y * 64;
    for (int i = threadIdx.x; i < 64 * Dd; i += 128)
        sy[i] = y[(size_t)t0 * Dd + i];
    __syncthreads();

    float w[Dd];
#pragma unroll
    for (int k = 0; k < Dd; k++) w[k] = W_ih1[(size_t)row * Dd + k];
    float b = b_ih1[row] + b_hh1[row];

    for (int tt = 0; tt < 64; tt++) {
        float acc = b;
#pragma unroll
        for (int k = 0; k < Dd; k++) acc += w[k] * sy[tt * Dd + k];
        g_pre1[(size_t)(t0 + tt) * G4H + row] = acc;
    }
}

// ---------------------------------------------------------------------------
// Kernel 2: persistent sequential LSTM. 148 blocks x 512 threads.
// Block b owns hidden indices [j0, j0+nj); per step:
//   phase1: gates1 = g_pre1[t] + W_hh1 @ h1      -> h1,c1 update -> barrier
//   phase2: gates2 = W_ih2 @ h1 + W_hh2 @ h2 + b -> h2,c2 update -> barrier
// h1/h2 double-buffered in global; c1/c2 block-private in smem; h2 history saved.
// ---------------------------------------------------------------------------
__global__ void __launch_bounds__(NTHR, 1)
lstm_kernel(const float* __restrict__ W_hh1,
            const float* __restrict__ W_ih2,
            const float* __restrict__ W_hh2,
            const float* __restrict__ b_ih2,
            const float* __restrict__ b_hh2) {
    __shared__ float sA[Hh];
    __shared__ float sB[Hh];
    __shared__ float sgate[64];
    __shared__ float sc1[16];
    __shared__ float sc2[16];

    const int tid = threadIdx.x;
    const int lane = tid & 31;
    const int warp = tid >> 5;
    const int b = blockIdx.x;

    const int base = Hh / NBLK;          // 13
    const int extra = Hh % NBLK;         // 124
    const int nj = base + (b < extra ? 1 : 0);
    const int j0 = b * base + (b < extra ? b : extra);
    const int nrows = 4 * nj;

    // init state
    for (int j = tid; j < nj; j += NTHR) {
        g_h1[0][j0 + j] = 0.f;
        g_h2[0][j0 + j] = 0.f;
    }
    if (tid < 16) { sc1[tid] = 0.f; sc2[tid] = 0.f; }
    grid_barrier();

    for (int t = 0; t < Tt; t++) {
        const int p = t & 1;

        // ---- phase 1: layer 1 ----
        for (int i = tid; i < Hh / 4; i += NTHR)
            ((float4*)sA)[i] = ((const float4*)g_h1[p])[i];
        __syncthreads();

        for (int lr = warp; lr < nrows; lr += NWARP) {
            int q = lr & 3, jj = lr >> 2;
            int row = q * Hh + j0 + jj;
            float s = warp_dot((const float4*)(W_hh1 + (size_t)row * Hh),
                               (const float4*)sA, lane);
            if (lane == 0) sgate[lr] = s + g_pre1[(size_t)t * G4H + row];
        }
        __syncthreads();

        if (tid < nj) {
            float gi = sigf(sgate[tid * 4 + 0]);
            float gf = sigf(sgate[tid * 4 + 1]);
            float gg = tanhf(sgate[tid * 4 + 2]);
            float go = sigf(sgate[tid * 4 + 3]);
            float c = gf * sc1[tid] + gi * gg;
            sc1[tid] = c;
            g_h1[1 - p][j0 + tid] = go * tanhf(c);
        }
        grid_barrier();

        // ---- phase 2: layer 2 ----
        for (int i = tid; i < Hh / 4; i += NTHR)
            ((float4*)sA)[i] = ((const float4*)g_h1[1 - p])[i];
        for (int i = tid; i < Hh / 4; i += NTHR)
            ((float4*)sB)[i] = ((const float4*)g_h2[p])[i];
        __syncthreads();

        for (int lr = warp; lr < nrows; lr += NWARP) {
            int q = lr & 3, jj = lr >> 2;
            int row = q * Hh + j0 + jj;
            float s = warp_dot((const float4*)(W_ih2 + (size_t)row * Hh),
                               (const float4*)sA, lane)
                    + warp_dot((const float4*)(W_hh2 + (size_t)row * Hh),
                               (const float4*)sB, lane);
            if (lane == 0) sgate[lr] = s + b_ih2[row] + b_hh2[row];
        }
        __syncthreads();

        if (tid < nj) {
            float gi = sigf(sgate[tid * 4 + 0]);
            float gf = sigf(sgate[tid * 4 + 1]);
            float gg = tanhf(sgate[tid * 4 + 2]);
            float go = sigf(sgate[tid * 4 + 3]);
            float c = gf * sc2[tid] + gi * gg;
            sc2[tid] = c;
            float hn = go * tanhf(c);
            g_h2[1 - p][j0 + tid] = hn;
            g_h2hist[t][j0 + tid] = hn;
        }
        grid_barrier();
    }
}

// ---------------------------------------------------------------------------
// Kernel 3: out[t-prelen][d] = b_lin[d] + W_lin[d,:] @ h2hist[t,:]
// One block per output timestep.
// ---------------------------------------------------------------------------
__global__ void proj_kernel(const float* __restrict__ W_lin,
                            const float* __restrict__ b_lin,
                            float* __restrict__ out,
                            int prelen) {
    __shared__ float sh[Hh];
    const int t = prelen + blockIdx.x;
    const int tid = threadIdx.x;
    const int lane = tid & 31;
    const int warp = tid >> 5;

    for (int i = tid; i < Hh / 4; i += 256)
        ((float4*)sh)[i] = ((const float4*)&g_h2hist[t][0])[i];
    __syncthreads();

    for (int d = warp; d < Dd; d += 8) {
        float s = warp_dot((const float4*)(W_lin + (size_t)d * Hh),
                           (const float4*)sh, lane);
        if (lane == 0) out[(size_t)blockIdx.x * Dd + d] = s + b_lin[d];
    }
}

extern "C" void kernel_launch(void* const* d_in, const int* in_sizes, int n_in,
                              void* d_out, int out_size) {
    const float* y     = (const float*)d_in[0];
    const float* W_ih1 = (const float*)d_in[1];
    const float* W_hh1 = (const float*)d_in[2];
    const float* b_ih1 = (const float*)d_in[3];
    const float* b_hh1 = (const float*)d_in[4];
    const float* W_ih2 = (const float*)d_in[5];
    const float* W_hh2 = (const float*)d_in[6];
    const float* b_ih2 = (const float*)d_in[7];
    const float* b_hh2 = (const float*)d_in[8];
    const float* W_lin = (const float*)d_in[9];
    const float* b_lin = (const float*)d_in[10];
    (void)in_sizes; (void)n_in;

    const int nt = out_size / Dd;          // T - pre_output_len (4032)
    const int prelen = Tt - nt;            // 64

    dim3 g1(G4H / 128, Tt / 64);
    pre1_kernel<<<g1, 128>>>(y, W_ih1, b_ih1, b_hh1);
    lstm_kernel<<<NBLK, NTHR>>>(W_hh1, W_ih2, W_hh2, b_ih2, b_hh2);
    proj_kernel<<<nt, 256>>>(W_lin, b_lin, (float*)d_out, prelen);
}

// round 3
// speedup vs baseline: 2.3700x; 2.3700x over previous
#include <cuda_runtime.h>
#include <cuda_fp16.h>
#include <math.h>

#define Hh 2048
#define Tt 4096
#define Dd 66
#define G4H (4*Hh)
#define NBLK 148
#define NTHR 512
#define NWARP (NTHR/32)
#define WELEM ((size_t)G4H*(size_t)Hh)   // 16.78M elements per weight matrix

// ---------------- persistent device state (static; no runtime allocs) -------
__device__ float  g_h1[2][Hh];
__device__ float  g_h2[2][Hh];
__device__ float  g_h2hist[Tt][Hh];                // 33.5 MB
__device__ float  g_pre1[(size_t)Tt * G4H];        // 134 MB
__device__ __half g_whh1[WELEM];                   // 33.5 MB fp16
__device__ __half g_wih2[WELEM];
__device__ __half g_whh2[WELEM];

// flag barrier state (monotonic across graph replays)
__device__ volatile unsigned g_arrive[NBLK];
__device__ volatile unsigned g_release;

__device__ __forceinline__ float sigf(float x) { return 1.0f / (1.0f + expf(-x)); }

// ---------------- flag-based grid barrier -----------------------------------
// target is monotonically increasing (base read from g_release at entry), so
// stale flags from a previous replay compare as "not yet arrived".
__device__ __forceinline__ void gbar(unsigned target) {
    __syncthreads();
    if (blockIdx.x == 0) {
        if (threadIdx.x > 0 && threadIdx.x < NBLK) {
            while ((int)(g_arrive[threadIdx.x] - target) < 0) { }
        }
        __syncthreads();
        if (threadIdx.x == 0) { __threadfence(); g_release = target; }
    } else {
        if (threadIdx.x == 0) {
            __threadfence();
            g_arrive[blockIdx.x] = target;
            while ((int)(g_release - target) < 0) { }
            __threadfence();
        }
    }
    __syncthreads();
}

// ---------------- helpers ----------------------------------------------------
__device__ __forceinline__ float wreduce(float s) {
#pragma unroll
    for (int o = 16; o; o >>= 1) s += __shfl_down_sync(0xffffffffu, s, o);
    return s;
}

__device__ __forceinline__ float cvdot(uint2 u, float4 h) {
    float2 f0 = __half22float2(*reinterpret_cast<__half2*>(&u.x));
    float2 f1 = __half22float2(*reinterpret_cast<__half2*>(&u.y));
    return f0.x * h.x + f0.y * h.y + f1.x * h.z + f1.y * h.w;
}

// Dot of 4 weight rows (fp16, row-major, 2048 each) against one fp32 vector in
// smem. Lane l covers elements 4*(k*32+l)..+3 : weight uint2 loads coalesced
// (256B/warp/row), h float4 LDS conflict-free, shared across the 4 rows.
__device__ __forceinline__ float4 dot4rows(const __half* __restrict__ w0,
                                           const __half* __restrict__ w1,
                                           const __half* __restrict__ w2,
                                           const __half* __restrict__ w3,
                                           const float4* __restrict__ hv,
                                           int lane) {
    float a0 = 0.f, a1 = 0.f, a2 = 0.f, a3 = 0.f;
#pragma unroll 4
    for (int k = 0; k < 16; k++) {
        int idx = k * 32 + lane;
        float4 h = hv[idx];
        a0 += cvdot(((const uint2*)w0)[idx], h);
        a1 += cvdot(((const uint2*)w1)[idx], h);
        a2 += cvdot(((const uint2*)w2)[idx], h);
        a3 += cvdot(((const uint2*)w3)[idx], h);
    }
    return make_float4(wreduce(a0), wreduce(a1), wreduce(a2), wreduce(a3));
}

// fp32 warp dot (used by proj kernel only)
__device__ __forceinline__ float warp_dot(const float4* __restrict__ w,
                                          const float4* __restrict__ sh,
                                          int lane) {
    float ax = 0.f, ay = 0.f, az = 0.f, aw = 0.f;
#pragma unroll
    for (int k = 0; k < 16; k++) {
        float4 wv = w[k * 32 + lane];
        float4 hv = sh[k * 32 + lane];
        ax += wv.x * hv.x; ay += wv.y * hv.y;
        az += wv.z * hv.z; aw += wv.w * hv.w;
    }
    return wreduce((ax + ay) + (az + aw));
}

// ---------------- kernel 0: fp32 -> fp16 weight conversion -------------------
__global__ void cvt_kernel(const float* __restrict__ A,
                           const float* __restrict__ B,
                           const float* __restrict__ C) {
    size_t n4 = WELEM / 4;
    size_t stride = (size_t)gridDim.x * blockDim.x;
    for (size_t i = (size_t)blockIdx.x * blockDim.x + threadIdx.x; i < n4; i += stride) {
        float4 a = ((const float4*)A)[i];
        float4 b = ((const float4*)B)[i];
        float4 c = ((const float4*)C)[i];
        ((__half2*)g_whh1)[2*i]   = __floats2half2_rn(a.x, a.y);
        ((__half2*)g_whh1)[2*i+1] = __floats2half2_rn(a.z, a.w);
        ((__half2*)g_wih2)[2*i]   = __floats2half2_rn(b.x, b.y);
        ((__half2*)g_wih2)[2*i+1] = __floats2half2_rn(b.z, b.w);
        ((__half2*)g_whh2)[2*i]   = __floats2half2_rn(c.x, c.y);
        ((__half2*)g_whh2)[2*i+1] = __floats2half2_rn(c.z, c.w);
    }
}

// ---------------- kernel 1: pre1[t][row] = b1 + W_ih1[row,:] @ y[t,:] --------
__global__ void pre1_kernel(const float* __restrict__ y,
                            const float* __restrict__ W_ih1,
                            const float* __restrict__ b_ih1,
                            const float* __restrict__ b_hh1) {
    __shared__ float sy[64 * Dd];
    int row = blockIdx.x * 128 + threadIdx.x;
    int t0 = blockIdx.y * 64;
    for (int i = threadIdx.x; i < 64 * Dd; i += 128)
        sy[i] = y[(size_t)t0 * Dd + i];
    __syncthreads();

    float w[Dd];
#pragma unroll
    for (int k = 0; k < Dd; k++) w[k] = W_ih1[(size_t)row * Dd + k];
    float b = b_ih1[row] + b_hh1[row];

    for (int tt = 0; tt < 64; tt++) {
        float acc = b;
#pragma unroll
        for (int k = 0; k < Dd; k++) acc += w[k] * sy[tt * Dd + k];
        g_pre1[(size_t)(t0 + tt) * G4H + row] = acc;
    }
}

// ---------------- kernel 2: persistent sequential LSTM -----------------------
__global__ void __launch_bounds__(NTHR, 1)
lstm_kernel(const float* __restrict__ b_ih2,
            const float* __restrict__ b_hh2) {
    __shared__ float sA[Hh];
    __shared__ float sB[Hh];
    __shared__ float sg1[64];
    __shared__ float sg2[2][64];
    __shared__ float sbias[64];
    __shared__ float sc1[16];
    __shared__ float sc2[16];

    const int tid  = threadIdx.x;
    const int lane = tid & 31;
    const int warp = tid >> 5;
    const int b    = blockIdx.x;

    const int base  = Hh / NBLK;          // 13
    const int extra = Hh % NBLK;          // 124
    const int nj = base + (b < extra ? 1 : 0);
    const int j0 = b * base + (b < extra ? b : extra);

    unsigned bgen = g_release;            // consistent base for this launch

    // init state + layer-2 bias cache
    for (int j = tid; j < nj; j += NTHR) {
        g_h1[0][j0 + j] = 0.f;
        g_h2[0][j0 + j] = 0.f;
    }
    for (int r = tid; r < 4 * nj; r += NTHR) {
        int j = r >> 2, q = r & 3;
        int row = q * Hh + j0 + j;
        sbias[r] = b_ih2[row] + b_hh2[row];
    }
    if (tid < 16) { sc1[tid] = 0.f; sc2[tid] = 0.f; }
    gbar(++bgen);

    for (int t = 0; t < Tt; t++) {
        const int p = t & 1;

        // ---- phase 1: layer 1 (gates = pre1[t] + W_hh1 @ h1) ----
        for (int i = tid; i < Hh / 4; i += NTHR)
            ((float4*)sA)[i] = ((const float4*)g_h1[p])[i];
        __syncthreads();

        for (int j = warp; j < nj; j += NWARP) {
            const __half* w = g_whh1 + (size_t)(j0 + j) * Hh;
            float4 r = dot4rows(w, w + (size_t)Hh * Hh, w + 2ull * Hh * Hh,
                                w + 3ull * Hh * Hh, (const float4*)sA, lane);
            if (lane == 0) {
                sg1[j * 4 + 0] = r.x; sg1[j * 4 + 1] = r.y;
                sg1[j * 4 + 2] = r.z; sg1[j * 4 + 3] = r.w;
            }
        }
        __syncthreads();

        if (tid < nj) {
            size_t pb = (size_t)t * G4H + j0 + tid;
            float gi = sigf (sg1[tid * 4 + 0] + g_pre1[pb]);
            float gf = sigf (sg1[tid * 4 + 1] + g_pre1[pb + Hh]);
            float gg = tanhf(sg1[tid * 4 + 2] + g_pre1[pb + 2 * Hh]);
            float go = sigf (sg1[tid * 4 + 3] + g_pre1[pb + 3 * Hh]);
            float c = gf * sc1[tid] + gi * gg;
            sc1[tid] = c;
            g_h1[1 - p][j0 + tid] = go * tanhf(c);
        }
        gbar(++bgen);

        // ---- phase 2: layer 2 (gates = W_ih2 @ h1 + W_hh2 @ h2 + b) ----
        for (int i = tid; i < Hh / 4; i += NTHR)
            ((float4*)sA)[i] = ((const float4*)g_h1[1 - p])[i];
        for (int i = tid; i < Hh / 4; i += NTHR)
            ((float4*)sB)[i] = ((const float4*)g_h2[p])[i];
        __syncthreads();

        for (int task = warp; task < 2 * nj; task += NWARP) {
            int m = (task >= nj);
            int j = task - m * nj;
            const __half*  wbase = m ? g_whh2 : g_wih2;
            const float4*  hv    = m ? (const float4*)sB : (const float4*)sA;
            const __half* w = wbase + (size_t)(j0 + j) * Hh;
            float4 r = dot4rows(w, w + (size_t)Hh * Hh, w + 2ull * Hh * Hh,
                                w + 3ull * Hh * Hh, hv, lane);
            if (lane == 0) {
                sg2[m][j * 4 + 0] = r.x; sg2[m][j * 4 + 1] = r.y;
                sg2[m][j * 4 + 2] = r.z; sg2[m][j * 4 + 3] = r.w;
            }
        }
        __syncthreads();

        if (tid < nj) {
            float gi = sigf (sg2[0][tid*4+0] + sg2[1][tid*4+0] + sbias[tid*4+0]);
            float gf = sigf (sg2[0][tid*4+1] + sg2[1][tid*4+1] + sbias[tid*4+1]);
            float gg = tanhf(sg2[0][tid*4+2] + sg2[1][tid*4+2] + sbias[tid*4+2]);
            float go = sigf (sg2[0][tid*4+3] + sg2[1][tid*4+3] + sbias[tid*4+3]);
            float c = gf * sc2[tid] + gi * gg;
            sc2[tid] = c;
            float hn = go * tanhf(c);
            g_h2[1 - p][j0 + tid] = hn;
            g_h2hist[t][j0 + tid] = hn;
        }
        gbar(++bgen);
    }
}

// ---------------- kernel 3: output projection --------------------------------
__global__ void proj_kernel(const float* __restrict__ W_lin,
                            const float* __restrict__ b_lin,
                            float* __restrict__ out,
                            int prelen) {
    __shared__ float sh[Hh];
    const int t = prelen + blockIdx.x;
    const int tid = threadIdx.x;
    const int lane = tid & 31;
    const int warp = tid >> 5;

    for (int i = tid; i < Hh / 4; i += 256)
        ((float4*)sh)[i] = ((const float4*)&g_h2hist[t][0])[i];
    __syncthreads();

    for (int d = warp; d < Dd; d += 8) {
        float s = warp_dot((const float4*)(W_lin + (size_t)d * Hh),
                           (const float4*)sh, lane);
        if (lane == 0) out[(size_t)blockIdx.x * Dd + d] = s + b_lin[d];
    }
}

extern "C" void kernel_launch(void* const* d_in, const int* in_sizes, int n_in,
                              void* d_out, int out_size) {
    const float* y     = (const float*)d_in[0];
    const float* W_ih1 = (const float*)d_in[1];
    const float* W_hh1 = (const float*)d_in[2];
    const float* b_ih1 = (const float*)d_in[3];
    const float* b_hh1 = (const float*)d_in[4];
    const float* W_ih2 = (const float*)d_in[5];
    const float* W_hh2 = (const float*)d_in[6];
    const float* b_ih2 = (const float*)d_in[7];
    const float* b_hh2 = (const float*)d_in[8];
    const float* W_lin = (const float*)d_in[9];
    const float* b_lin = (const float*)d_in[10];
    (void)in_sizes; (void)n_in;

    const int nt = out_size / Dd;          // T - pre_output_len
    const int prelen = Tt - nt;

    cvt_kernel<<<2048, 256>>>(W_hh1, W_ih2, W_hh2);
    dim3 g1(G4H / 128, Tt / 64);
    pre1_kernel<<<g1, 128>>>(y, W_ih1, b_ih1, b_hh1);
    lstm_kernel<<<NBLK, NTHR>>>(b_ih2, b_hh2);
    proj_kernel<<<nt, 256>>>(W_lin, b_lin, (float*)d_out, prelen);
}